// round 1
// baseline (speedup 1.0000x reference)
#include <cuda_runtime.h>

namespace {
constexpr int P    = 32;
constexpr int Cin  = 9;
constexpr int H    = 64;
constexpr int OUTC = 128;
constexpr float EPS = 1e-5f;
}

#define LOAD_W8(ptr, w)                                                     \
  {                                                                         \
    float4 wa_ = __ldg((const float4*)(ptr));                               \
    float4 wb_ = __ldg((const float4*)((ptr) + 4));                         \
    w[0]=wa_.x; w[1]=wa_.y; w[2]=wa_.z; w[3]=wa_.w;                         \
    w[4]=wb_.x; w[5]=wb_.y; w[6]=wb_.z; w[7]=wb_.w;                         \
  }

__global__ void __launch_bounds__(64)
pnet_kernel(const float* __restrict__ poly,
            const void*  __restrict__ mask,
            const float* __restrict__ pre_w, const float* __restrict__ pre_b,
            const float* __restrict__ pre_g, const float* __restrict__ pre_be,
            const float* __restrict__ pre_rm, const float* __restrict__ pre_rv,
            const float* __restrict__ m1_w,  const float* __restrict__ m1_b,
            const float* __restrict__ m1_g,  const float* __restrict__ m1_be,
            const float* __restrict__ m1_rm, const float* __restrict__ m1_rv,
            const float* __restrict__ m2_w,  const float* __restrict__ m2_b,
            const float* __restrict__ m2_g,  const float* __restrict__ m2_be,
            const float* __restrict__ m2_rm, const float* __restrict__ m2_rv,
            const float* __restrict__ o1_w,  const float* __restrict__ o1_b,
            const float* __restrict__ o2_w,  const float* __restrict__ o2_b,
            float* __restrict__ out)
{
  // fT: activation tile, transposed [channel][point], row stride 36 floats
  // (144B, 16B-aligned) so rows start on distinct banks for the pooling pass.
  __shared__ __align__(16) float fT[H][P + 4];
  __shared__ float pts[P][12];     // input points, padded row
  __shared__ float mk[P];          // mask as 0/1 float
  __shared__ float pooled[H];
  __shared__ float pctr[H];        // pooled @ m1_w[64:128,:]  (shared across points)
  __shared__ float feat[H];
  __shared__ float hid[H];
  __shared__ int   s_mode, s_valid;

  const int blk = blockIdx.x;          // polyline index in [0, B*N)
  const int tid = threadIdx.x;         // 0..63
  const int cg  = tid & 7;             // channel group (8 groups of 8)
  const int pg  = tid >> 3;            // point group   (8 groups of 4)
  const int h0  = cg * 8;
  const int p0  = pg * 4;

  // ---- mask dtype detection (bool/uint8 vs int32 vs float32) ----
  if (tid == 0) {
    const unsigned* w32 = (const unsigned*)mask;
    bool big = false, allf = true;
    #pragma unroll
    for (int i = 0; i < 32; i++) {
      unsigned v = w32[i];
      big  |= (v > 1u);
      allf &= (v == 0u || v == 0x3f800000u);
    }
    s_mode = big ? (allf ? 1 : 2) : 0;  // 0=int32, 1=float32, 2=byte
  }
  __syncthreads();
  const int mode = s_mode;

  // ---- load points + mask ----
  const float* pp = poly + (long long)blk * (P * Cin);
  for (int i = tid; i < P * Cin; i += 64) pts[i / Cin][i % Cin] = pp[i];

  if (tid < 32) {
    int gi = blk * P + tid;
    float mv;
    if (mode == 2)      mv = ((const unsigned char*)mask)[gi] ? 1.f : 0.f;
    else if (mode == 1) mv = (((const float*)mask)[gi] != 0.f) ? 1.f : 0.f;
    else                mv = ((const int*)mask)[gi] ? 1.f : 0.f;
    mk[tid] = mv;
    unsigned bal = __ballot_sync(0xffffffffu, mv != 0.f);
    if (tid == 0) s_valid = (bal != 0u) ? 1 : 0;
  }
  __syncthreads();

  float acc[4][8];
  float w[8];

  // ================= pre layer: [P,9] @ [9,64] =================
  #pragma unroll
  for (int i = 0; i < 4; i++)
    #pragma unroll
    for (int j = 0; j < 8; j++) acc[i][j] = 0.f;

  #pragma unroll
  for (int k = 0; k < Cin; k++) {
    float x0 = pts[p0 + 0][k], x1 = pts[p0 + 1][k];
    float x2 = pts[p0 + 2][k], x3 = pts[p0 + 3][k];
    LOAD_W8(pre_w + k * H + h0, w);
    #pragma unroll
    for (int j = 0; j < 8; j++) {
      acc[0][j] = fmaf(x0, w[j], acc[0][j]);
      acc[1][j] = fmaf(x1, w[j], acc[1][j]);
      acc[2][j] = fmaf(x2, w[j], acc[2][j]);
      acc[3][j] = fmaf(x3, w[j], acc[3][j]);
    }
  }
  {
    float A[8], Bc[8];
    #pragma unroll
    for (int j = 0; j < 8; j++) {
      int h = h0 + j;
      float s = __ldg(&pre_g[h]) * rsqrtf(__ldg(&pre_rv[h]) + EPS);
      A[j]  = s;
      Bc[j] = (__ldg(&pre_b[h]) - __ldg(&pre_rm[h])) * s + __ldg(&pre_be[h]);
    }
    float mv0 = mk[p0], mv1 = mk[p0 + 1], mv2 = mk[p0 + 2], mv3 = mk[p0 + 3];
    #pragma unroll
    for (int j = 0; j < 8; j++) {
      float4 v;
      v.x = fmaxf(fmaf(acc[0][j], A[j], Bc[j]), 0.f) * mv0;
      v.y = fmaxf(fmaf(acc[1][j], A[j], Bc[j]), 0.f) * mv1;
      v.z = fmaxf(fmaf(acc[2][j], A[j], Bc[j]), 0.f) * mv2;
      v.w = fmaxf(fmaf(acc[3][j], A[j], Bc[j]), 0.f) * mv3;
      *(float4*)&fT[h0 + j][p0] = v;
    }
  }
  __syncthreads();

  // ================= max-pool over points (channel = tid) =================
  {
    const float4* row = (const float4*)&fT[tid][0];
    float m = 0.f;   // all values >= 0 (ReLU + masked zeros)
    #pragma unroll
    for (int g = 0; g < 8; g++) {
      float4 v = row[g];
      m = fmaxf(m, fmaxf(fmaxf(v.x, v.y), fmaxf(v.z, v.w)));
    }
    pooled[tid] = m;
  }
  __syncthreads();

  // pooled contribution through second half of m1_w — once per polyline
  {
    float a = 0.f;
    #pragma unroll 8
    for (int k = 0; k < H; k++)
      a = fmaf(pooled[k], __ldg(&m1_w[(H + k) * H + tid]), a);
    pctr[tid] = a;
  }
  __syncthreads();

  // ================= m1: [P,64(f)] @ m1_w[0:64,:] + pctr =================
  #pragma unroll
  for (int j = 0; j < 8; j++) {
    float c = pctr[h0 + j];
    acc[0][j] = c; acc[1][j] = c; acc[2][j] = c; acc[3][j] = c;
  }
  #pragma unroll 8
  for (int k = 0; k < H; k++) {
    float4 xv = *(const float4*)&fT[k][p0];
    LOAD_W8(m1_w + k * H + h0, w);
    #pragma unroll
    for (int j = 0; j < 8; j++) {
      acc[0][j] = fmaf(xv.x, w[j], acc[0][j]);
      acc[1][j] = fmaf(xv.y, w[j], acc[1][j]);
      acc[2][j] = fmaf(xv.z, w[j], acc[2][j]);
      acc[3][j] = fmaf(xv.w, w[j], acc[3][j]);
    }
  }
  {
    float A[8], Bc[8];
    #pragma unroll
    for (int j = 0; j < 8; j++) {
      int h = h0 + j;
      float s = __ldg(&m1_g[h]) * rsqrtf(__ldg(&m1_rv[h]) + EPS);
      A[j]  = s;
      Bc[j] = (__ldg(&m1_b[h]) - __ldg(&m1_rm[h])) * s + __ldg(&m1_be[h]);
    }
    float v[4][8];
    #pragma unroll
    for (int j = 0; j < 8; j++)
      #pragma unroll
      for (int i = 0; i < 4; i++)
        v[i][j] = fmaxf(fmaf(acc[i][j], A[j], Bc[j]), 0.f);
    __syncthreads();   // all reads of fT done; safe to overwrite
    #pragma unroll
    for (int j = 0; j < 8; j++) {
      float4 o = make_float4(v[0][j], v[1][j], v[2][j], v[3][j]);
      *(float4*)&fT[h0 + j][p0] = o;
    }
  }
  __syncthreads();

  // ================= m2: [P,64] @ [64,64], masked =================
  #pragma unroll
  for (int i = 0; i < 4; i++)
    #pragma unroll
    for (int j = 0; j < 8; j++) acc[i][j] = 0.f;

  #pragma unroll 8
  for (int k = 0; k < H; k++) {
    float4 xv = *(const float4*)&fT[k][p0];
    LOAD_W8(m2_w + k * H + h0, w);
    #pragma unroll
    for (int j = 0; j < 8; j++) {
      acc[0][j] = fmaf(xv.x, w[j], acc[0][j]);
      acc[1][j] = fmaf(xv.y, w[j], acc[1][j]);
      acc[2][j] = fmaf(xv.z, w[j], acc[2][j]);
      acc[3][j] = fmaf(xv.w, w[j], acc[3][j]);
    }
  }
  {
    float A[8], Bc[8];
    #pragma unroll
    for (int j = 0; j < 8; j++) {
      int h = h0 + j;
      float s = __ldg(&m2_g[h]) * rsqrtf(__ldg(&m2_rv[h]) + EPS);
      A[j]  = s;
      Bc[j] = (__ldg(&m2_b[h]) - __ldg(&m2_rm[h])) * s + __ldg(&m2_be[h]);
    }
    float mv0 = mk[p0], mv1 = mk[p0 + 1], mv2 = mk[p0 + 2], mv3 = mk[p0 + 3];
    float v[4][8];
    #pragma unroll
    for (int j = 0; j < 8; j++) {
      v[0][j] = fmaxf(fmaf(acc[0][j], A[j], Bc[j]), 0.f) * mv0;
      v[1][j] = fmaxf(fmaf(acc[1][j], A[j], Bc[j]), 0.f) * mv1;
      v[2][j] = fmaxf(fmaf(acc[2][j], A[j], Bc[j]), 0.f) * mv2;
      v[3][j] = fmaxf(fmaf(acc[3][j], A[j], Bc[j]), 0.f) * mv3;
    }
    __syncthreads();
    #pragma unroll
    for (int j = 0; j < 8; j++) {
      float4 o = make_float4(v[0][j], v[1][j], v[2][j], v[3][j]);
      *(float4*)&fT[h0 + j][p0] = o;
    }
  }
  __syncthreads();

  // ================= feat = max-pool over points =================
  {
    const float4* row = (const float4*)&fT[tid][0];
    float m = 0.f;
    #pragma unroll
    for (int g = 0; g < 8; g++) {
      float4 v = row[g];
      m = fmaxf(m, fmaxf(fmaxf(v.x, v.y), fmaxf(v.z, v.w)));
    }
    feat[tid] = m;
  }
  __syncthreads();

  // ================= head: relu(feat@o1_w + o1_b) @ o2_w + o2_b ============
  {
    float a = __ldg(&o1_b[tid]);
    #pragma unroll 8
    for (int k = 0; k < H; k++)
      a = fmaf(feat[k], __ldg(&o1_w[k * H + tid]), a);
    hid[tid] = fmaxf(a, 0.f);
  }
  __syncthreads();

  {
    float vflag = s_valid ? 1.f : 0.f;
    #pragma unroll
    for (int rep = 0; rep < 2; rep++) {
      int j = tid + rep * 64;
      float a = __ldg(&o2_b[j]);
      #pragma unroll 8
      for (int k = 0; k < H; k++)
        a = fmaf(hid[k], __ldg(&o2_w[k * OUTC + j]), a);
      out[(long long)blk * OUTC + j] = a * vflag;
    }
  }
}

extern "C" void kernel_launch(void* const* d_in, const int* in_sizes, int n_in,
                              void* d_out, int out_size)
{
  (void)in_sizes; (void)n_in;
  const int n_poly = out_size / OUTC;   // B*N = 16384
  pnet_kernel<<<n_poly, 64>>>(
      (const float*)d_in[0],  d_in[1],
      (const float*)d_in[2],  (const float*)d_in[3],
      (const float*)d_in[4],  (const float*)d_in[5],
      (const float*)d_in[6],  (const float*)d_in[7],
      (const float*)d_in[8],  (const float*)d_in[9],
      (const float*)d_in[10], (const float*)d_in[11],
      (const float*)d_in[12], (const float*)d_in[13],
      (const float*)d_in[14], (const float*)d_in[15],
      (const float*)d_in[16], (const float*)d_in[17],
      (const float*)d_in[18], (const float*)d_in[19],
      (const float*)d_in[20], (const float*)d_in[21],
      (const float*)d_in[22], (const float*)d_in[23],
      (float*)d_out);
}

// round 3
// speedup vs baseline: 1.1867x; 1.1867x over previous
#include <cuda_runtime.h>

namespace {
constexpr int P    = 32;
constexpr int Cin  = 9;
constexpr int H    = 64;
constexpr int OUTC = 128;
constexpr int FS   = 68;   // fT row stride in floats (16B-aligned rows)
constexpr float EPS = 1e-5f;
}

using ull = unsigned long long;

__device__ __forceinline__ ull fma2(ull a, ull b, ull c) {
  ull d;
  asm("fma.rn.f32x2 %0, %1, %2, %3;" : "=l"(d) : "l"(a), "l"(b), "l"(c));
  return d;
}
__device__ __forceinline__ ull dup2(float x) {
  ull d; unsigned u = __float_as_uint(x);
  asm("mov.b64 %0, {%1, %1};" : "=l"(d) : "r"(u));
  return d;
}
__device__ __forceinline__ ull pack2(float lo, float hi) {
  ull d;
  asm("mov.b64 %0, {%1, %2};" : "=l"(d)
      : "r"(__float_as_uint(lo)), "r"(__float_as_uint(hi)));
  return d;
}
__device__ __forceinline__ float2 unpk(ull v) {
  unsigned a, b;
  asm("mov.b64 {%0, %1}, %2;" : "=r"(a), "=r"(b) : "l"(v));
  return make_float2(__uint_as_float(a), __uint_as_float(b));
}
// 16B weight load -> two packed channel pairs
__device__ __forceinline__ void ldgw(const float* p, ull& a, ull& b) {
  asm("ld.global.nc.v2.u64 {%0, %1}, [%2];" : "=l"(a), "=l"(b) : "l"(p));
}
// BN fold for a channel pair
__device__ __forceinline__ void bn2(const float* g, const float* be,
                                    const float* rm, const float* rv,
                                    const float* b, int h, ull& A2, ull& B2) {
  float s0 = __ldg(&g[h])     * rsqrtf(__ldg(&rv[h])     + EPS);
  float s1 = __ldg(&g[h + 1]) * rsqrtf(__ldg(&rv[h + 1]) + EPS);
  float c0 = (__ldg(&b[h])     - __ldg(&rm[h]))     * s0 + __ldg(&be[h]);
  float c1 = (__ldg(&b[h + 1]) - __ldg(&rm[h + 1])) * s1 + __ldg(&be[h + 1]);
  A2 = pack2(s0, s1);
  B2 = pack2(c0, c1);
}

__global__ void __launch_bounds__(64)
pnet_kernel(const float* __restrict__ poly,
            const void*  __restrict__ mask,
            const float* __restrict__ pre_w, const float* __restrict__ pre_b,
            const float* __restrict__ pre_g, const float* __restrict__ pre_be,
            const float* __restrict__ pre_rm, const float* __restrict__ pre_rv,
            const float* __restrict__ m1_w,  const float* __restrict__ m1_b,
            const float* __restrict__ m1_g,  const float* __restrict__ m1_be,
            const float* __restrict__ m1_rm, const float* __restrict__ m1_rv,
            const float* __restrict__ m2_w,  const float* __restrict__ m2_b,
            const float* __restrict__ m2_g,  const float* __restrict__ m2_be,
            const float* __restrict__ m2_rm, const float* __restrict__ m2_rv,
            const float* __restrict__ o1_w,  const float* __restrict__ o1_b,
            const float* __restrict__ o2_w,  const float* __restrict__ o2_b,
            float* __restrict__ out)
{
  // fT[point][channel]: writes are channel-contiguous STS.128,
  // k-loop reads are per-k column broadcasts (4 distinct addrs/warp).
  __shared__ __align__(16) float fT[P][FS];
  __shared__ float pts[P][12];
  __shared__ float mk[P];
  __shared__ float pooled[H];
  __shared__ float pctr[H];
  __shared__ float feat[H];
  __shared__ float hid[H];
  __shared__ int   s_mode, s_valid;

  const int blk = blockIdx.x;
  const int tid = threadIdx.x;        // 0..63
  const int cg  = tid & 7;            // channel group: 8 groups of 8 channels
  const int pg  = tid >> 3;           // point group:   8 groups of 4 points
  const int h0  = cg * 8;
  const int p0  = pg * 4;

  // ---- mask dtype detection (int32 vs float32 vs byte) ----
  if (tid == 0) {
    const unsigned* w32 = (const unsigned*)mask;
    bool big = false, allf = true;
    #pragma unroll
    for (int i = 0; i < 32; i++) {
      unsigned v = w32[i];
      big  |= (v > 1u);
      allf &= (v == 0u || v == 0x3f800000u);
    }
    s_mode = big ? (allf ? 1 : 2) : 0;
  }
  __syncthreads();
  const int mode = s_mode;

  // ---- load points + mask ----
  const float* pp = poly + (long long)blk * (P * Cin);
  for (int i = tid; i < P * Cin; i += 64) pts[i / Cin][i % Cin] = pp[i];

  if (tid < 32) {
    int gi = blk * P + tid;
    float mv;
    if (mode == 2)      mv = ((const unsigned char*)mask)[gi] ? 1.f : 0.f;
    else if (mode == 1) mv = (((const float*)mask)[gi] != 0.f) ? 1.f : 0.f;
    else                mv = ((const int*)mask)[gi] ? 1.f : 0.f;
    mk[tid] = mv;
    unsigned bal = __ballot_sync(0xffffffffu, mv != 0.f);
    if (tid == 0) s_valid = (bal != 0u) ? 1 : 0;
  }
  __syncthreads();

  ull acc[4][4];      // [point i][channel-pair j]
  ull w01, w23, w45, w67;
  ull A2[4], B2[4];

  // ================= pre layer: [P,9] @ [9,64] =================
  #pragma unroll
  for (int i = 0; i < 4; i++)
    #pragma unroll
    for (int j = 0; j < 4; j++) acc[i][j] = 0ull;

  #pragma unroll
  for (int k = 0; k < Cin; k++) {
    ull x0 = dup2(pts[p0 + 0][k]);
    ull x1 = dup2(pts[p0 + 1][k]);
    ull x2 = dup2(pts[p0 + 2][k]);
    ull x3 = dup2(pts[p0 + 3][k]);
    const float* wr = pre_w + k * H + h0;
    ldgw(wr, w01, w23);
    ldgw(wr + 4, w45, w67);
    acc[0][0] = fma2(x0, w01, acc[0][0]); acc[0][1] = fma2(x0, w23, acc[0][1]);
    acc[0][2] = fma2(x0, w45, acc[0][2]); acc[0][3] = fma2(x0, w67, acc[0][3]);
    acc[1][0] = fma2(x1, w01, acc[1][0]); acc[1][1] = fma2(x1, w23, acc[1][1]);
    acc[1][2] = fma2(x1, w45, acc[1][2]); acc[1][3] = fma2(x1, w67, acc[1][3]);
    acc[2][0] = fma2(x2, w01, acc[2][0]); acc[2][1] = fma2(x2, w23, acc[2][1]);
    acc[2][2] = fma2(x2, w45, acc[2][2]); acc[2][3] = fma2(x2, w67, acc[2][3]);
    acc[3][0] = fma2(x3, w01, acc[3][0]); acc[3][1] = fma2(x3, w23, acc[3][1]);
    acc[3][2] = fma2(x3, w45, acc[3][2]); acc[3][3] = fma2(x3, w67, acc[3][3]);
  }
  #pragma unroll
  for (int j = 0; j < 4; j++) bn2(pre_g, pre_be, pre_rm, pre_rv, pre_b, h0 + 2 * j, A2[j], B2[j]);
  {
    #pragma unroll
    for (int i = 0; i < 4; i++) {
      float mv = mk[p0 + i];
      float2 r0 = unpk(fma2(acc[i][0], A2[0], B2[0]));
      float2 r1 = unpk(fma2(acc[i][1], A2[1], B2[1]));
      float2 r2 = unpk(fma2(acc[i][2], A2[2], B2[2]));
      float2 r3 = unpk(fma2(acc[i][3], A2[3], B2[3]));
      float4 s0 = make_float4(fmaxf(r0.x, 0.f) * mv, fmaxf(r0.y, 0.f) * mv,
                              fmaxf(r1.x, 0.f) * mv, fmaxf(r1.y, 0.f) * mv);
      float4 s1 = make_float4(fmaxf(r2.x, 0.f) * mv, fmaxf(r2.y, 0.f) * mv,
                              fmaxf(r3.x, 0.f) * mv, fmaxf(r3.y, 0.f) * mv);
      *(float4*)&fT[p0 + i][h0]     = s0;
      *(float4*)&fT[p0 + i][h0 + 4] = s1;
    }
  }
  __syncthreads();

  // ================= max-pool over points (channel = tid) =================
  {
    float m = 0.f;
    #pragma unroll
    for (int p = 0; p < P; p++) m = fmaxf(m, fT[p][tid]);
    pooled[tid] = m;
  }
  __syncthreads();

  // pooled @ m1_w[64:128,:] — once per polyline
  {
    float a = 0.f;
    #pragma unroll 8
    for (int k = 0; k < H; k++)
      a = fmaf(pooled[k], __ldg(&m1_w[(H + k) * H + tid]), a);
    pctr[tid] = a;
  }
  __syncthreads();

  // ================= m1: [P,64] @ m1_w[0:64,:] + pctr =================
  #pragma unroll
  for (int j = 0; j < 4; j++) {
    float2 pc = *(const float2*)&pctr[h0 + 2 * j];
    ull c = pack2(pc.x, pc.y);
    acc[0][j] = c; acc[1][j] = c; acc[2][j] = c; acc[3][j] = c;
  }
  #pragma unroll 8
  for (int k = 0; k < H; k++) {
    ull x0 = dup2(fT[p0 + 0][k]);
    ull x1 = dup2(fT[p0 + 1][k]);
    ull x2 = dup2(fT[p0 + 2][k]);
    ull x3 = dup2(fT[p0 + 3][k]);
    const float* wr = m1_w + k * H + h0;
    ldgw(wr, w01, w23);
    ldgw(wr + 4, w45, w67);
    acc[0][0] = fma2(x0, w01, acc[0][0]); acc[0][1] = fma2(x0, w23, acc[0][1]);
    acc[0][2] = fma2(x0, w45, acc[0][2]); acc[0][3] = fma2(x0, w67, acc[0][3]);
    acc[1][0] = fma2(x1, w01, acc[1][0]); acc[1][1] = fma2(x1, w23, acc[1][1]);
    acc[1][2] = fma2(x1, w45, acc[1][2]); acc[1][3] = fma2(x1, w67, acc[1][3]);
    acc[2][0] = fma2(x2, w01, acc[2][0]); acc[2][1] = fma2(x2, w23, acc[2][1]);
    acc[2][2] = fma2(x2, w45, acc[2][2]); acc[2][3] = fma2(x2, w67, acc[2][3]);
    acc[3][0] = fma2(x3, w01, acc[3][0]); acc[3][1] = fma2(x3, w23, acc[3][1]);
    acc[3][2] = fma2(x3, w45, acc[3][2]); acc[3][3] = fma2(x3, w67, acc[3][3]);
  }
  #pragma unroll
  for (int j = 0; j < 4; j++) bn2(m1_g, m1_be, m1_rm, m1_rv, m1_b, h0 + 2 * j, A2[j], B2[j]);
  {
    float4 s[4][2];
    #pragma unroll
    for (int i = 0; i < 4; i++) {
      float2 r0 = unpk(fma2(acc[i][0], A2[0], B2[0]));
      float2 r1 = unpk(fma2(acc[i][1], A2[1], B2[1]));
      float2 r2 = unpk(fma2(acc[i][2], A2[2], B2[2]));
      float2 r3 = unpk(fma2(acc[i][3], A2[3], B2[3]));
      s[i][0] = make_float4(fmaxf(r0.x, 0.f), fmaxf(r0.y, 0.f),
                            fmaxf(r1.x, 0.f), fmaxf(r1.y, 0.f));
      s[i][1] = make_float4(fmaxf(r2.x, 0.f), fmaxf(r2.y, 0.f),
                            fmaxf(r3.x, 0.f), fmaxf(r3.y, 0.f));
    }
    __syncthreads();   // all fT reads done; safe to overwrite
    #pragma unroll
    for (int i = 0; i < 4; i++) {
      *(float4*)&fT[p0 + i][h0]     = s[i][0];
      *(float4*)&fT[p0 + i][h0 + 4] = s[i][1];
    }
  }
  __syncthreads();

  // ================= m2: [P,64] @ [64,64], masked =================
  #pragma unroll
  for (int i = 0; i < 4; i++)
    #pragma unroll
    for (int j = 0; j < 4; j++) acc[i][j] = 0ull;

  #pragma unroll 8
  for (int k = 0; k < H; k++) {
    ull x0 = dup2(fT[p0 + 0][k]);
    ull x1 = dup2(fT[p0 + 1][k]);
    ull x2 = dup2(fT[p0 + 2][k]);
    ull x3 = dup2(fT[p0 + 3][k]);
    const float* wr = m2_w + k * H + h0;
    ldgw(wr, w01, w23);
    ldgw(wr + 4, w45, w67);
    acc[0][0] = fma2(x0, w01, acc[0][0]); acc[0][1] = fma2(x0, w23, acc[0][1]);
    acc[0][2] = fma2(x0, w45, acc[0][2]); acc[0][3] = fma2(x0, w67, acc[0][3]);
    acc[1][0] = fma2(x1, w01, acc[1][0]); acc[1][1] = fma2(x1, w23, acc[1][1]);
    acc[1][2] = fma2(x1, w45, acc[1][2]); acc[1][3] = fma2(x1, w67, acc[1][3]);
    acc[2][0] = fma2(x2, w01, acc[2][0]); acc[2][1] = fma2(x2, w23, acc[2][1]);
    acc[2][2] = fma2(x2, w45, acc[2][2]); acc[2][3] = fma2(x2, w67, acc[2][3]);
    acc[3][0] = fma2(x3, w01, acc[3][0]); acc[3][1] = fma2(x3, w23, acc[3][1]);
    acc[3][2] = fma2(x3, w45, acc[3][2]); acc[3][3] = fma2(x3, w67, acc[3][3]);
  }
  #pragma unroll
  for (int j = 0; j < 4; j++) bn2(m2_g, m2_be, m2_rm, m2_rv, m2_b, h0 + 2 * j, A2[j], B2[j]);
  {
    float4 s[4][2];
    #pragma unroll
    for (int i = 0; i < 4; i++) {
      float mv = mk[p0 + i];
      float2 r0 = unpk(fma2(acc[i][0], A2[0], B2[0]));
      float2 r1 = unpk(fma2(acc[i][1], A2[1], B2[1]));
      float2 r2 = unpk(fma2(acc[i][2], A2[2], B2[2]));
      float2 r3 = unpk(fma2(acc[i][3], A2[3], B2[3]));
      s[i][0] = make_float4(fmaxf(r0.x, 0.f) * mv, fmaxf(r0.y, 0.f) * mv,
                            fmaxf(r1.x, 0.f) * mv, fmaxf(r1.y, 0.f) * mv);
      s[i][1] = make_float4(fmaxf(r2.x, 0.f) * mv, fmaxf(r2.y, 0.f) * mv,
                            fmaxf(r3.x, 0.f) * mv, fmaxf(r3.y, 0.f) * mv);
    }
    __syncthreads();
    #pragma unroll
    for (int i = 0; i < 4; i++) {
      *(float4*)&fT[p0 + i][h0]     = s[i][0];
      *(float4*)&fT[p0 + i][h0 + 4] = s[i][1];
    }
  }
  __syncthreads();

  // ================= feat = max-pool over points =================
  {
    float m = 0.f;
    #pragma unroll
    for (int p = 0; p < P; p++) m = fmaxf(m, fT[p][tid]);
    feat[tid] = m;
  }
  __syncthreads();

  // ================= head =================
  {
    float a = __ldg(&o1_b[tid]);
    #pragma unroll 8
    for (int k = 0; k < H; k++)
      a = fmaf(feat[k], __ldg(&o1_w[k * H + tid]), a);
    hid[tid] = fmaxf(a, 0.f);
  }
  __syncthreads();

  {
    float vflag = s_valid ? 1.f : 0.f;
    #pragma unroll
    for (int rep = 0; rep < 2; rep++) {
      int j = tid + rep * 64;
      float a = __ldg(&o2_b[j]);
      #pragma unroll 8
      for (int k = 0; k < H; k++)
        a = fmaf(hid[k], __ldg(&o2_w[k * OUTC + j]), a);
      out[(long long)blk * OUTC + j] = a * vflag;
    }
  }
}

extern "C" void kernel_launch(void* const* d_in, const int* in_sizes, int n_in,
                              void* d_out, int out_size)
{
  (void)in_sizes; (void)n_in;
  const int n_poly = out_size / OUTC;   // B*N = 16384
  pnet_kernel<<<n_poly, 64>>>(
      (const float*)d_in[0],  d_in[1],
      (const float*)d_in[2],  (const float*)d_in[3],
      (const float*)d_in[4],  (const float*)d_in[5],
      (const float*)d_in[6],  (const float*)d_in[7],
      (const float*)d_in[8],  (const float*)d_in[9],
      (const float*)d_in[10], (const float*)d_in[11],
      (const float*)d_in[12], (const float*)d_in[13],
      (const float*)d_in[14], (const float*)d_in[15],
      (const float*)d_in[16], (const float*)d_in[17],
      (const float*)d_in[18], (const float*)d_in[19],
      (const float*)d_in[20], (const float*)d_in[21],
      (const float*)d_in[22], (const float*)d_in[23],
      (float*)d_out);
}

// round 4
// speedup vs baseline: 1.4965x; 1.2610x over previous
#include <cuda_runtime.h>

namespace {
constexpr int P    = 32;
constexpr int Cin  = 9;
constexpr int H    = 64;
constexpr int OUTC = 128;
constexpr int FS   = 36;   // fT row stride (floats); 16B-aligned rows
constexpr float EPS = 1e-5f;
}

using ull = unsigned long long;

__device__ __forceinline__ ull fma2(ull a, ull b, ull c) {
  ull d;
  asm("fma.rn.f32x2 %0, %1, %2, %3;" : "=l"(d) : "l"(a), "l"(b), "l"(c));
  return d;
}
__device__ __forceinline__ ull dup2(float x) {
  ull d; unsigned u = __float_as_uint(x);
  asm("mov.b64 %0, {%1, %1};" : "=l"(d) : "r"(u));
  return d;
}
__device__ __forceinline__ ull pack2(float lo, float hi) {
  ull d;
  asm("mov.b64 %0, {%1, %2};" : "=l"(d)
      : "r"(__float_as_uint(lo)), "r"(__float_as_uint(hi)));
  return d;
}
__device__ __forceinline__ float2 unpk(ull v) {
  unsigned a, b;
  asm("mov.b64 {%0, %1}, %2;" : "=r"(a), "=r"(b) : "l"(v));
  return make_float2(__uint_as_float(a), __uint_as_float(b));
}
__device__ __forceinline__ void ldgw(const float* p, ull& a, ull& b) {
  asm("ld.global.nc.v2.u64 {%0, %1}, [%2];" : "=l"(a), "=l"(b) : "l"(p));
}
__device__ __forceinline__ void bn2(const float* g, const float* be,
                                    const float* rm, const float* rv,
                                    const float* b, int h, ull& A2, ull& B2) {
  float s0 = __ldg(&g[h])     * rsqrtf(__ldg(&rv[h])     + EPS);
  float s1 = __ldg(&g[h + 1]) * rsqrtf(__ldg(&rv[h + 1]) + EPS);
  float c0 = (__ldg(&b[h])     - __ldg(&rm[h]))     * s0 + __ldg(&be[h]);
  float c1 = (__ldg(&b[h + 1]) - __ldg(&rm[h + 1])) * s1 + __ldg(&be[h + 1]);
  A2 = pack2(s0, s1);
  B2 = pack2(c0, c1);
}

// 16 packed FMAs: x for 4 points (dup'd), weights for 8 channels (4 pairs)
#define MMA_STEP(X0, X1, X2, X3)                                             \
  {                                                                          \
    acc[0][0] = fma2(X0, w01, acc[0][0]); acc[0][1] = fma2(X0, w23, acc[0][1]); \
    acc[0][2] = fma2(X0, w45, acc[0][2]); acc[0][3] = fma2(X0, w67, acc[0][3]); \
    acc[1][0] = fma2(X1, w01, acc[1][0]); acc[1][1] = fma2(X1, w23, acc[1][1]); \
    acc[1][2] = fma2(X1, w45, acc[1][2]); acc[1][3] = fma2(X1, w67, acc[1][3]); \
    acc[2][0] = fma2(X2, w01, acc[2][0]); acc[2][1] = fma2(X2, w23, acc[2][1]); \
    acc[2][2] = fma2(X2, w45, acc[2][2]); acc[2][3] = fma2(X2, w67, acc[2][3]); \
    acc[3][0] = fma2(X3, w01, acc[3][0]); acc[3][1] = fma2(X3, w23, acc[3][1]); \
    acc[3][2] = fma2(X3, w45, acc[3][2]); acc[3][3] = fma2(X3, w67, acc[3][3]); \
  }

__global__ void __launch_bounds__(64)
pnet_kernel(const float* __restrict__ poly,
            const void*  __restrict__ mask,
            const float* __restrict__ pre_w, const float* __restrict__ pre_b,
            const float* __restrict__ pre_g, const float* __restrict__ pre_be,
            const float* __restrict__ pre_rm, const float* __restrict__ pre_rv,
            const float* __restrict__ m1_w,  const float* __restrict__ m1_b,
            const float* __restrict__ m1_g,  const float* __restrict__ m1_be,
            const float* __restrict__ m1_rm, const float* __restrict__ m1_rv,
            const float* __restrict__ m2_w,  const float* __restrict__ m2_b,
            const float* __restrict__ m2_g,  const float* __restrict__ m2_be,
            const float* __restrict__ m2_rm, const float* __restrict__ m2_rv,
            const float* __restrict__ o1_w,  const float* __restrict__ o1_b,
            const float* __restrict__ o2_w,  const float* __restrict__ o2_b,
            float* __restrict__ out)
{
  // fT[channel][point]: k-loop x-read = one LDS.128 per thread; per warp the
  // 8 point-groups cover one contiguous 128B row -> 1 wavefront.
  __shared__ __align__(16) float fT[H][FS];
  __shared__ float pts[P][12];
  __shared__ float mk[P];
  __shared__ float pooled[H];
  __shared__ float pctr[H];
  __shared__ float feat[H];
  __shared__ float hid[H];
  __shared__ int   s_mode, s_valid;

  const int blk = blockIdx.x;
  const int tid = threadIdx.x;        // 0..63
  const int cg  = tid >> 3;           // channel group: warp0 -> ch 0..31, warp1 -> 32..63
  const int pg  = tid & 7;            // point group
  const int h0  = cg * 8;
  const int p0  = pg * 4;

  // ---- mask dtype detection (int32 vs float32 vs byte) ----
  if (tid == 0) {
    const unsigned* w32 = (const unsigned*)mask;
    bool big = false, allf = true;
    #pragma unroll
    for (int i = 0; i < 32; i++) {
      unsigned v = w32[i];
      big  |= (v > 1u);
      allf &= (v == 0u || v == 0x3f800000u);
    }
    s_mode = big ? (allf ? 1 : 2) : 0;
  }
  __syncthreads();
  const int mode = s_mode;

  // ---- load points + mask ----
  const float* pp = poly + (long long)blk * (P * Cin);
  for (int i = tid; i < P * Cin; i += 64) pts[i / Cin][i % Cin] = pp[i];

  if (tid < 32) {
    int gi = blk * P + tid;
    float mv;
    if (mode == 2)      mv = ((const unsigned char*)mask)[gi] ? 1.f : 0.f;
    else if (mode == 1) mv = (((const float*)mask)[gi] != 0.f) ? 1.f : 0.f;
    else                mv = ((const int*)mask)[gi] ? 1.f : 0.f;
    mk[tid] = mv;
    unsigned bal = __ballot_sync(0xffffffffu, mv != 0.f);
    if (tid == 0) s_valid = (bal != 0u) ? 1 : 0;
  }
  __syncthreads();

  ull acc[4][4];      // [point i][channel-pair j]
  ull w01, w23, w45, w67;
  ull A2[4], B2[4];

  // ================= pre layer: [P,9] @ [9,64] =================
  #pragma unroll
  for (int i = 0; i < 4; i++)
    #pragma unroll
    for (int j = 0; j < 4; j++) acc[i][j] = 0ull;

  #pragma unroll
  for (int k = 0; k < Cin; k++) {
    ull x0 = dup2(pts[p0 + 0][k]);
    ull x1 = dup2(pts[p0 + 1][k]);
    ull x2 = dup2(pts[p0 + 2][k]);
    ull x3 = dup2(pts[p0 + 3][k]);
    const float* wr = pre_w + k * H + h0;
    ldgw(wr, w01, w23);
    ldgw(wr + 4, w45, w67);
    MMA_STEP(x0, x1, x2, x3)
  }
  #pragma unroll
  for (int j = 0; j < 4; j++) bn2(pre_g, pre_be, pre_rm, pre_rv, pre_b, h0 + 2 * j, A2[j], B2[j]);
  {
    float mv0 = mk[p0], mv1 = mk[p0 + 1], mv2 = mk[p0 + 2], mv3 = mk[p0 + 3];
    #pragma unroll
    for (int j = 0; j < 4; j++) {
      float2 r0 = unpk(fma2(acc[0][j], A2[j], B2[j]));
      float2 r1 = unpk(fma2(acc[1][j], A2[j], B2[j]));
      float2 r2 = unpk(fma2(acc[2][j], A2[j], B2[j]));
      float2 r3 = unpk(fma2(acc[3][j], A2[j], B2[j]));
      *(float4*)&fT[h0 + 2 * j][p0] =
        make_float4(fmaxf(r0.x, 0.f) * mv0, fmaxf(r1.x, 0.f) * mv1,
                    fmaxf(r2.x, 0.f) * mv2, fmaxf(r3.x, 0.f) * mv3);
      *(float4*)&fT[h0 + 2 * j + 1][p0] =
        make_float4(fmaxf(r0.y, 0.f) * mv0, fmaxf(r1.y, 0.f) * mv1,
                    fmaxf(r2.y, 0.f) * mv2, fmaxf(r3.y, 0.f) * mv3);
    }
  }
  __syncthreads();

  // ================= max-pool over points (channel = tid) =================
  {
    const float4* row = (const float4*)&fT[tid][0];
    float m = 0.f;
    #pragma unroll
    for (int g = 0; g < 8; g++) {
      float4 v = row[g];
      m = fmaxf(m, fmaxf(fmaxf(v.x, v.y), fmaxf(v.z, v.w)));
    }
    pooled[tid] = m;
  }
  __syncthreads();

  // pooled @ m1_w[64:128,:] — once per polyline
  {
    float a = 0.f;
    #pragma unroll 8
    for (int k = 0; k < H; k++)
      a = fmaf(pooled[k], __ldg(&m1_w[(H + k) * H + tid]), a);
    pctr[tid] = a;
  }
  __syncthreads();

  // ================= m1: [P,64] @ m1_w[0:64,:] + pctr =================
  #pragma unroll
  for (int j = 0; j < 4; j++) {
    float2 pc = *(const float2*)&pctr[h0 + 2 * j];
    ull c = pack2(pc.x, pc.y);
    acc[0][j] = c; acc[1][j] = c; acc[2][j] = c; acc[3][j] = c;
  }
  #pragma unroll 8
  for (int k = 0; k < H; k++) {
    float4 xv = *(const float4*)&fT[k][p0];
    ull x0 = dup2(xv.x), x1 = dup2(xv.y), x2 = dup2(xv.z), x3 = dup2(xv.w);
    const float* wr = m1_w + k * H + h0;
    ldgw(wr, w01, w23);
    ldgw(wr + 4, w45, w67);
    MMA_STEP(x0, x1, x2, x3)
  }
  #pragma unroll
  for (int j = 0; j < 4; j++) bn2(m1_g, m1_be, m1_rm, m1_rv, m1_b, h0 + 2 * j, A2[j], B2[j]);
  {
    float4 s[4][2];
    #pragma unroll
    for (int j = 0; j < 4; j++) {
      float2 r0 = unpk(fma2(acc[0][j], A2[j], B2[j]));
      float2 r1 = unpk(fma2(acc[1][j], A2[j], B2[j]));
      float2 r2 = unpk(fma2(acc[2][j], A2[j], B2[j]));
      float2 r3 = unpk(fma2(acc[3][j], A2[j], B2[j]));
      s[j][0] = make_float4(fmaxf(r0.x, 0.f), fmaxf(r1.x, 0.f),
                            fmaxf(r2.x, 0.f), fmaxf(r3.x, 0.f));
      s[j][1] = make_float4(fmaxf(r0.y, 0.f), fmaxf(r1.y, 0.f),
                            fmaxf(r2.y, 0.f), fmaxf(r3.y, 0.f));
    }
    __syncthreads();   // all fT reads done; safe to overwrite
    #pragma unroll
    for (int j = 0; j < 4; j++) {
      *(float4*)&fT[h0 + 2 * j][p0]     = s[j][0];
      *(float4*)&fT[h0 + 2 * j + 1][p0] = s[j][1];
    }
  }
  __syncthreads();

  // ================= m2: [P,64] @ [64,64], masked =================
  #pragma unroll
  for (int i = 0; i < 4; i++)
    #pragma unroll
    for (int j = 0; j < 4; j++) acc[i][j] = 0ull;

  #pragma unroll 8
  for (int k = 0; k < H; k++) {
    float4 xv = *(const float4*)&fT[k][p0];
    ull x0 = dup2(xv.x), x1 = dup2(xv.y), x2 = dup2(xv.z), x3 = dup2(xv.w);
    const float* wr = m2_w + k * H + h0;
    ldgw(wr, w01, w23);
    ldgw(wr + 4, w45, w67);
    MMA_STEP(x0, x1, x2, x3)
  }
  #pragma unroll
  for (int j = 0; j < 4; j++) bn2(m2_g, m2_be, m2_rm, m2_rv, m2_b, h0 + 2 * j, A2[j], B2[j]);
  {
    float mv0 = mk[p0], mv1 = mk[p0 + 1], mv2 = mk[p0 + 2], mv3 = mk[p0 + 3];
    float4 s[4][2];
    #pragma unroll
    for (int j = 0; j < 4; j++) {
      float2 r0 = unpk(fma2(acc[0][j], A2[j], B2[j]));
      float2 r1 = unpk(fma2(acc[1][j], A2[j], B2[j]));
      float2 r2 = unpk(fma2(acc[2][j], A2[j], B2[j]));
      float2 r3 = unpk(fma2(acc[3][j], A2[j], B2[j]));
      s[j][0] = make_float4(fmaxf(r0.x, 0.f) * mv0, fmaxf(r1.x, 0.f) * mv1,
                            fmaxf(r2.x, 0.f) * mv2, fmaxf(r3.x, 0.f) * mv3);
      s[j][1] = make_float4(fmaxf(r0.y, 0.f) * mv0, fmaxf(r1.y, 0.f) * mv1,
                            fmaxf(r2.y, 0.f) * mv2, fmaxf(r3.y, 0.f) * mv3);
    }
    __syncthreads();
    #pragma unroll
    for (int j = 0; j < 4; j++) {
      *(float4*)&fT[h0 + 2 * j][p0]     = s[j][0];
      *(float4*)&fT[h0 + 2 * j + 1][p0] = s[j][1];
    }
  }
  __syncthreads();

  // ================= feat = max-pool over points =================
  {
    const float4* row = (const float4*)&fT[tid][0];
    float m = 0.f;
    #pragma unroll
    for (int g = 0; g < 8; g++) {
      float4 v = row[g];
      m = fmaxf(m, fmaxf(fmaxf(v.x, v.y), fmaxf(v.z, v.w)));
    }
    feat[tid] = m;
  }
  __syncthreads();

  // ================= head =================
  {
    float a = __ldg(&o1_b[tid]);
    #pragma unroll 8
    for (int k = 0; k < H; k++)
      a = fmaf(feat[k], __ldg(&o1_w[k * H + tid]), a);
    hid[tid] = fmaxf(a, 0.f);
  }
  __syncthreads();

  {
    float vflag = s_valid ? 1.f : 0.f;
    #pragma unroll
    for (int rep = 0; rep < 2; rep++) {
      int j = tid + rep * 64;
      float a = __ldg(&o2_b[j]);
      #pragma unroll 8
      for (int k = 0; k < H; k++)
        a = fmaf(hid[k], __ldg(&o2_w[k * OUTC + j]), a);
      out[(long long)blk * OUTC + j] = a * vflag;
    }
  }
}

extern "C" void kernel_launch(void* const* d_in, const int* in_sizes, int n_in,
                              void* d_out, int out_size)
{
  (void)in_sizes; (void)n_in;
  const int n_poly = out_size / OUTC;   // B*N = 16384
  pnet_kernel<<<n_poly, 64>>>(
      (const float*)d_in[0],  d_in[1],
      (const float*)d_in[2],  (const float*)d_in[3],
      (const float*)d_in[4],  (const float*)d_in[5],
      (const float*)d_in[6],  (const float*)d_in[7],
      (const float*)d_in[8],  (const float*)d_in[9],
      (const float*)d_in[10], (const float*)d_in[11],
      (const float*)d_in[12], (const float*)d_in[13],
      (const float*)d_in[14], (const float*)d_in[15],
      (const float*)d_in[16], (const float*)d_in[17],
      (const float*)d_in[18], (const float*)d_in[19],
      (const float*)d_in[20], (const float*)d_in[21],
      (const float*)d_in[22], (const float*)d_in[23],
      (float*)d_out);
}

// round 5
// speedup vs baseline: 1.6990x; 1.1353x over previous
#include <cuda_runtime.h>

namespace {
constexpr int P    = 32;
constexpr int Cin  = 9;
constexpr int H    = 64;
constexpr int OUTC = 128;
constexpr int FS   = 36;   // fT row stride (floats); 16B-aligned rows
constexpr float EPS = 1e-5f;
}

using ull = unsigned long long;

__device__ __forceinline__ ull fma2(ull a, ull b, ull c) {
  ull d;
  asm("fma.rn.f32x2 %0, %1, %2, %3;" : "=l"(d) : "l"(a), "l"(b), "l"(c));
  return d;
}
__device__ __forceinline__ ull dup2(float x) {
  ull d; unsigned u = __float_as_uint(x);
  asm("mov.b64 %0, {%1, %1};" : "=l"(d) : "r"(u));
  return d;
}
__device__ __forceinline__ ull pack2(float lo, float hi) {
  ull d;
  asm("mov.b64 %0, {%1, %2};" : "=l"(d)
      : "r"(__float_as_uint(lo)), "r"(__float_as_uint(hi)));
  return d;
}
__device__ __forceinline__ float2 unpk(ull v) {
  unsigned a, b;
  asm("mov.b64 {%0, %1}, %2;" : "=r"(a), "=r"(b) : "l"(v));
  return make_float2(__uint_as_float(a), __uint_as_float(b));
}
__device__ __forceinline__ void ldgw(const float* p, ull& a, ull& b) {
  asm("ld.global.nc.v2.u64 {%0, %1}, [%2];" : "=l"(a), "=l"(b) : "l"(p));
}
__device__ __forceinline__ void bn2(const float* g, const float* be,
                                    const float* rm, const float* rv,
                                    const float* b, int h, ull& A2, ull& B2) {
  float s0 = __ldg(&g[h])     * rsqrtf(__ldg(&rv[h])     + EPS);
  float s1 = __ldg(&g[h + 1]) * rsqrtf(__ldg(&rv[h + 1]) + EPS);
  float c0 = (__ldg(&b[h])     - __ldg(&rm[h]))     * s0 + __ldg(&be[h]);
  float c1 = (__ldg(&b[h + 1]) - __ldg(&rm[h + 1])) * s1 + __ldg(&be[h + 1]);
  A2 = pack2(s0, s1);
  B2 = pack2(c0, c1);
}

// 16 packed FMAs for one polyline's 4 points against 4 weight pairs
#define MMA_STEP(A, X0, X1, X2, X3)                                           \
  {                                                                           \
    A[0][0] = fma2(X0, w01, A[0][0]); A[0][1] = fma2(X0, w23, A[0][1]);       \
    A[0][2] = fma2(X0, w45, A[0][2]); A[0][3] = fma2(X0, w67, A[0][3]);       \
    A[1][0] = fma2(X1, w01, A[1][0]); A[1][1] = fma2(X1, w23, A[1][1]);       \
    A[1][2] = fma2(X1, w45, A[1][2]); A[1][3] = fma2(X1, w67, A[1][3]);       \
    A[2][0] = fma2(X2, w01, A[2][0]); A[2][1] = fma2(X2, w23, A[2][1]);       \
    A[2][2] = fma2(X2, w45, A[2][2]); A[2][3] = fma2(X2, w67, A[2][3]);       \
    A[3][0] = fma2(X3, w01, A[3][0]); A[3][1] = fma2(X3, w23, A[3][1]);       \
    A[3][2] = fma2(X3, w45, A[3][2]); A[3][3] = fma2(X3, w67, A[3][3]);       \
  }

__global__ void __launch_bounds__(64)
pnet_kernel(const float* __restrict__ poly,
            const void*  __restrict__ mask,
            const float* __restrict__ pre_w, const float* __restrict__ pre_b,
            const float* __restrict__ pre_g, const float* __restrict__ pre_be,
            const float* __restrict__ pre_rm, const float* __restrict__ pre_rv,
            const float* __restrict__ m1_w,  const float* __restrict__ m1_b,
            const float* __restrict__ m1_g,  const float* __restrict__ m1_be,
            const float* __restrict__ m1_rm, const float* __restrict__ m1_rv,
            const float* __restrict__ m2_w,  const float* __restrict__ m2_b,
            const float* __restrict__ m2_g,  const float* __restrict__ m2_be,
            const float* __restrict__ m2_rm, const float* __restrict__ m2_rv,
            const float* __restrict__ o1_w,  const float* __restrict__ o1_b,
            const float* __restrict__ o2_w,  const float* __restrict__ o2_b,
            float* __restrict__ out)
{
  // Two polylines per CTA; weight fetches shared between them.
  __shared__ __align__(16) float fT[2][H][FS];
  __shared__ float pts[2][P][12];
  __shared__ float mk[2][P];
  __shared__ float pooled[2][H];
  __shared__ float pctr[2][H];
  __shared__ float feat[2][H];
  __shared__ float hid[2][H];
  __shared__ int   s_mode;
  __shared__ int   s_valid[2];

  const int blk = blockIdx.x;          // handles polylines 2*blk, 2*blk+1
  const int tid = threadIdx.x;         // 0..63
  const int cg  = tid >> 3;            // warp0 -> ch 0..31, warp1 -> 32..63
  const int pg  = tid & 7;
  const int h0  = cg * 8;
  const int p0  = pg * 4;

  // ---- mask dtype detection (int32 vs float32 vs byte) ----
  if (tid == 0) {
    const unsigned* w32 = (const unsigned*)mask;
    bool big = false, allf = true;
    #pragma unroll
    for (int i = 0; i < 32; i++) {
      unsigned v = w32[i];
      big  |= (v > 1u);
      allf &= (v == 0u || v == 0x3f800000u);
    }
    s_mode = big ? (allf ? 1 : 2) : 0;
  }
  __syncthreads();
  const int mode = s_mode;

  // ---- load points + mask for both polylines ----
  {
    const float* pp = poly + (long long)(2 * blk) * (P * Cin);
    for (int i = tid; i < 2 * P * Cin; i += 64) {
      int q = i / (P * Cin), r = i % (P * Cin);
      pts[q][r / Cin][r % Cin] = pp[i];
    }
  }
  {
    int q = tid >> 5, t = tid & 31;
    int gi = (2 * blk + q) * P + t;
    float mv;
    if (mode == 2)      mv = ((const unsigned char*)mask)[gi] ? 1.f : 0.f;
    else if (mode == 1) mv = (((const float*)mask)[gi] != 0.f) ? 1.f : 0.f;
    else                mv = ((const int*)mask)[gi] ? 1.f : 0.f;
    mk[q][t] = mv;
    unsigned bal = __ballot_sync(0xffffffffu, mv != 0.f);
    if (t == 0) s_valid[q] = (bal != 0u) ? 1 : 0;
  }
  __syncthreads();

  ull acc0[4][4], acc1[4][4];
  ull w01, w23, w45, w67;
  ull A2[4], B2[4];

  // ================= pre layer: [P,9] @ [9,64], both polylines =============
  #pragma unroll
  for (int i = 0; i < 4; i++)
    #pragma unroll
    for (int j = 0; j < 4; j++) { acc0[i][j] = 0ull; acc1[i][j] = 0ull; }

  #pragma unroll
  for (int k = 0; k < Cin; k++) {
    const float* wr = pre_w + k * H + h0;
    ldgw(wr, w01, w23);
    ldgw(wr + 4, w45, w67);
    ull x0 = dup2(pts[0][p0 + 0][k]);
    ull x1 = dup2(pts[0][p0 + 1][k]);
    ull x2 = dup2(pts[0][p0 + 2][k]);
    ull x3 = dup2(pts[0][p0 + 3][k]);
    MMA_STEP(acc0, x0, x1, x2, x3)
    x0 = dup2(pts[1][p0 + 0][k]);
    x1 = dup2(pts[1][p0 + 1][k]);
    x2 = dup2(pts[1][p0 + 2][k]);
    x3 = dup2(pts[1][p0 + 3][k]);
    MMA_STEP(acc1, x0, x1, x2, x3)
  }
  #pragma unroll
  for (int j = 0; j < 4; j++) bn2(pre_g, pre_be, pre_rm, pre_rv, pre_b, h0 + 2 * j, A2[j], B2[j]);
  #pragma unroll
  for (int q = 0; q < 2; q++) {
    ull (*ac)[4] = q ? acc1 : acc0;
    float mv0 = mk[q][p0], mv1 = mk[q][p0 + 1], mv2 = mk[q][p0 + 2], mv3 = mk[q][p0 + 3];
    #pragma unroll
    for (int j = 0; j < 4; j++) {
      float2 r0 = unpk(fma2(ac[0][j], A2[j], B2[j]));
      float2 r1 = unpk(fma2(ac[1][j], A2[j], B2[j]));
      float2 r2 = unpk(fma2(ac[2][j], A2[j], B2[j]));
      float2 r3 = unpk(fma2(ac[3][j], A2[j], B2[j]));
      *(float4*)&fT[q][h0 + 2 * j][p0] =
        make_float4(fmaxf(r0.x, 0.f) * mv0, fmaxf(r1.x, 0.f) * mv1,
                    fmaxf(r2.x, 0.f) * mv2, fmaxf(r3.x, 0.f) * mv3);
      *(float4*)&fT[q][h0 + 2 * j + 1][p0] =
        make_float4(fmaxf(r0.y, 0.f) * mv0, fmaxf(r1.y, 0.f) * mv1,
                    fmaxf(r2.y, 0.f) * mv2, fmaxf(r3.y, 0.f) * mv3);
    }
  }
  __syncthreads();

  // ========= max-pool over points (channel = tid, both polylines) =========
  #pragma unroll
  for (int q = 0; q < 2; q++) {
    const float4* row = (const float4*)&fT[q][tid][0];
    float m = 0.f;
    #pragma unroll
    for (int g = 0; g < 8; g++) {
      float4 v = row[g];
      m = fmaxf(m, fmaxf(fmaxf(v.x, v.y), fmaxf(v.z, v.w)));
    }
    pooled[q][tid] = m;
  }
  __syncthreads();

  // pctr = pooled @ m1_w[64:128,:]  (both polylines share weight loads)
  {
    ull a = 0ull;
    #pragma unroll 8
    for (int k = 0; k < H; k++) {
      float wv = __ldg(&m1_w[(H + k) * H + tid]);
      a = fma2(pack2(pooled[0][k], pooled[1][k]), dup2(wv), a);
    }
    float2 r = unpk(a);
    pctr[0][tid] = r.x;
    pctr[1][tid] = r.y;
  }
  __syncthreads();

  // ================= m1: [P,64] @ m1_w[0:64,:] + pctr =================
  #pragma unroll
  for (int j = 0; j < 4; j++) {
    float2 c0 = *(const float2*)&pctr[0][h0 + 2 * j];
    float2 c1 = *(const float2*)&pctr[1][h0 + 2 * j];
    ull p0c = pack2(c0.x, c0.y), p1c = pack2(c1.x, c1.y);
    acc0[0][j] = p0c; acc0[1][j] = p0c; acc0[2][j] = p0c; acc0[3][j] = p0c;
    acc1[0][j] = p1c; acc1[1][j] = p1c; acc1[2][j] = p1c; acc1[3][j] = p1c;
  }
  #pragma unroll 4
  for (int k = 0; k < H; k++) {
    const float* wr = m1_w + k * H + h0;
    ldgw(wr, w01, w23);
    ldgw(wr + 4, w45, w67);
    float4 xv = *(const float4*)&fT[0][k][p0];
    ull x0 = dup2(xv.x), x1 = dup2(xv.y), x2 = dup2(xv.z), x3 = dup2(xv.w);
    MMA_STEP(acc0, x0, x1, x2, x3)
    xv = *(const float4*)&fT[1][k][p0];
    x0 = dup2(xv.x); x1 = dup2(xv.y); x2 = dup2(xv.z); x3 = dup2(xv.w);
    MMA_STEP(acc1, x0, x1, x2, x3)
  }
  #pragma unroll
  for (int j = 0; j < 4; j++) bn2(m1_g, m1_be, m1_rm, m1_rv, m1_b, h0 + 2 * j, A2[j], B2[j]);
  {
    float4 s[2][4][2];
    #pragma unroll
    for (int q = 0; q < 2; q++) {
      ull (*ac)[4] = q ? acc1 : acc0;
      #pragma unroll
      for (int j = 0; j < 4; j++) {
        float2 r0 = unpk(fma2(ac[0][j], A2[j], B2[j]));
        float2 r1 = unpk(fma2(ac[1][j], A2[j], B2[j]));
        float2 r2 = unpk(fma2(ac[2][j], A2[j], B2[j]));
        float2 r3 = unpk(fma2(ac[3][j], A2[j], B2[j]));
        s[q][j][0] = make_float4(fmaxf(r0.x, 0.f), fmaxf(r1.x, 0.f),
                                 fmaxf(r2.x, 0.f), fmaxf(r3.x, 0.f));
        s[q][j][1] = make_float4(fmaxf(r0.y, 0.f), fmaxf(r1.y, 0.f),
                                 fmaxf(r2.y, 0.f), fmaxf(r3.y, 0.f));
      }
    }
    __syncthreads();   // all fT reads done; safe to overwrite
    #pragma unroll
    for (int q = 0; q < 2; q++)
      #pragma unroll
      for (int j = 0; j < 4; j++) {
        *(float4*)&fT[q][h0 + 2 * j][p0]     = s[q][j][0];
        *(float4*)&fT[q][h0 + 2 * j + 1][p0] = s[q][j][1];
      }
  }
  __syncthreads();

  // ================= m2: [P,64] @ [64,64], masked =================
  #pragma unroll
  for (int i = 0; i < 4; i++)
    #pragma unroll
    for (int j = 0; j < 4; j++) { acc0[i][j] = 0ull; acc1[i][j] = 0ull; }

  #pragma unroll 4
  for (int k = 0; k < H; k++) {
    const float* wr = m2_w + k * H + h0;
    ldgw(wr, w01, w23);
    ldgw(wr + 4, w45, w67);
    float4 xv = *(const float4*)&fT[0][k][p0];
    ull x0 = dup2(xv.x), x1 = dup2(xv.y), x2 = dup2(xv.z), x3 = dup2(xv.w);
    MMA_STEP(acc0, x0, x1, x2, x3)
    xv = *(const float4*)&fT[1][k][p0];
    x0 = dup2(xv.x); x1 = dup2(xv.y); x2 = dup2(xv.z); x3 = dup2(xv.w);
    MMA_STEP(acc1, x0, x1, x2, x3)
  }
  #pragma unroll
  for (int j = 0; j < 4; j++) bn2(m2_g, m2_be, m2_rm, m2_rv, m2_b, h0 + 2 * j, A2[j], B2[j]);
  {
    float4 s[2][4][2];
    #pragma unroll
    for (int q = 0; q < 2; q++) {
      ull (*ac)[4] = q ? acc1 : acc0;
      float mv0 = mk[q][p0], mv1 = mk[q][p0 + 1], mv2 = mk[q][p0 + 2], mv3 = mk[q][p0 + 3];
      #pragma unroll
      for (int j = 0; j < 4; j++) {
        float2 r0 = unpk(fma2(ac[0][j], A2[j], B2[j]));
        float2 r1 = unpk(fma2(ac[1][j], A2[j], B2[j]));
        float2 r2 = unpk(fma2(ac[2][j], A2[j], B2[j]));
        float2 r3 = unpk(fma2(ac[3][j], A2[j], B2[j]));
        s[q][j][0] = make_float4(fmaxf(r0.x, 0.f) * mv0, fmaxf(r1.x, 0.f) * mv1,
                                 fmaxf(r2.x, 0.f) * mv2, fmaxf(r3.x, 0.f) * mv3);
        s[q][j][1] = make_float4(fmaxf(r0.y, 0.f) * mv0, fmaxf(r1.y, 0.f) * mv1,
                                 fmaxf(r2.y, 0.f) * mv2, fmaxf(r3.y, 0.f) * mv3);
      }
    }
    __syncthreads();
    #pragma unroll
    for (int q = 0; q < 2; q++)
      #pragma unroll
      for (int j = 0; j < 4; j++) {
        *(float4*)&fT[q][h0 + 2 * j][p0]     = s[q][j][0];
        *(float4*)&fT[q][h0 + 2 * j + 1][p0] = s[q][j][1];
      }
  }
  __syncthreads();

  // ================= feat = max-pool over points =================
  #pragma unroll
  for (int q = 0; q < 2; q++) {
    const float4* row = (const float4*)&fT[q][tid][0];
    float m = 0.f;
    #pragma unroll
    for (int g = 0; g < 8; g++) {
      float4 v = row[g];
      m = fmaxf(m, fmaxf(fmaxf(v.x, v.y), fmaxf(v.z, v.w)));
    }
    feat[q][tid] = m;
  }
  __syncthreads();

  // ================= head (weight loads shared across polylines) ===========
  {
    ull a = dup2(__ldg(&o1_b[tid]));
    #pragma unroll 8
    for (int k = 0; k < H; k++) {
      float wv = __ldg(&o1_w[k * H + tid]);
      a = fma2(pack2(feat[0][k], feat[1][k]), dup2(wv), a);
    }
    float2 r = unpk(a);
    hid[0][tid] = fmaxf(r.x, 0.f);
    hid[1][tid] = fmaxf(r.y, 0.f);
  }
  __syncthreads();

  {
    float vf0 = s_valid[0] ? 1.f : 0.f;
    float vf1 = s_valid[1] ? 1.f : 0.f;
    #pragma unroll
    for (int rep = 0; rep < 2; rep++) {
      int j = tid + rep * 64;
      ull a = dup2(__ldg(&o2_b[j]));
      #pragma unroll 8
      for (int k = 0; k < H; k++) {
        float wv = __ldg(&o2_w[k * OUTC + j]);
        a = fma2(pack2(hid[0][k], hid[1][k]), dup2(wv), a);
      }
      float2 r = unpk(a);
      out[(long long)(2 * blk) * OUTC + j]     = r.x * vf0;
      out[(long long)(2 * blk + 1) * OUTC + j] = r.y * vf1;
    }
  }
}

extern "C" void kernel_launch(void* const* d_in, const int* in_sizes, int n_in,
                              void* d_out, int out_size)
{
  (void)in_sizes; (void)n_in;
  const int n_poly = out_size / OUTC;   // B*N = 16384 (even)
  pnet_kernel<<<n_poly / 2, 64>>>(
      (const float*)d_in[0],  d_in[1],
      (const float*)d_in[2],  (const float*)d_in[3],
      (const float*)d_in[4],  (const float*)d_in[5],
      (const float*)d_in[6],  (const float*)d_in[7],
      (const float*)d_in[8],  (const float*)d_in[9],
      (const float*)d_in[10], (const float*)d_in[11],
      (const float*)d_in[12], (const float*)d_in[13],
      (const float*)d_in[14], (const float*)d_in[15],
      (const float*)d_in[16], (const float*)d_in[17],
      (const float*)d_in[18], (const float*)d_in[19],
      (const float*)d_in[20], (const float*)d_in[21],
      (const float*)d_in[22], (const float*)d_in[23],
      (float*)d_out);
}